// round 3
// baseline (speedup 1.0000x reference)
#include <cuda_runtime.h>
#include <math.h>

#define B_ROWS 32768
#define F_DIM  2668

// Scratch for the 4 big embeddings: [B, 256] = uu|ui|tu|ti (64 cols each)
__device__ float g_Ebig[(size_t)B_ROWS * 256];

// ---------------------------------------------------------------------------
// SGEMM: C[M,128] = A[M,K] * Bmat[K,128]
//   Bmat[k][n] = (n < 64) ? W0[k*64+n] : W1[k*64+n-64]
//   A row-major with lda=F_DIM (A may be an unaligned column offset -> scalar loads)
//   C = g_Ebig[:, colOff:colOff+128], ldc = 256
// Tile: BM=128, BN=128, BK=8, 256 threads, 8x8 micro-tile, double-buffered smem.
// ---------------------------------------------------------------------------
__global__ __launch_bounds__(256, 2)
void gemm128_kernel(const float* __restrict__ A, int K,
                    const float* __restrict__ W0, const float* __restrict__ W1,
                    int colOff)
{
    __shared__ float As[2][8][128];   // [buf][k][m]
    __shared__ float Bs[2][8][128];   // [buf][k][n]

    const int tid   = threadIdx.x;
    const int aRow  = tid >> 1;          // 0..127
    const int aKoff = (tid & 1) * 4;     // 0 or 4
    const int bKoff = tid >> 5;          // 0..7
    const int bNoff = (tid & 31) * 4;    // 0..124
    const int mBase = (tid >> 4) * 8;    // 0..120
    const int nBase = (tid & 15) * 8;    // 0..120

    const float* Arow = A + (size_t)(blockIdx.x * 128 + aRow) * F_DIM;
    const float* Wsel = (bNoff < 64) ? (W0 + bNoff) : (W1 + (bNoff - 64));

    float acc[8][8];
    #pragma unroll
    for (int i = 0; i < 8; i++)
        #pragma unroll
        for (int j = 0; j < 8; j++) acc[i][j] = 0.0f;

    const int numTiles = (K + 7) >> 3;

    // ---- load tile 0 into buffer 0 ----
    {
        #pragma unroll
        for (int j = 0; j < 4; j++) {
            int kg = aKoff + j;
            As[0][aKoff + j][aRow] = (kg < K) ? Arow[kg] : 0.0f;
        }
        float4 bv = make_float4(0.f, 0.f, 0.f, 0.f);
        if (bKoff < K) bv = *(const float4*)(Wsel + (size_t)bKoff * 64);
        *(float4*)&Bs[0][bKoff][bNoff] = bv;
    }
    __syncthreads();

    int buf = 0;
    for (int t = 0; t < numTiles; t++) {
        // ---- prefetch next tile into registers ----
        float  an[4];
        float4 bn = make_float4(0.f, 0.f, 0.f, 0.f);
        const bool hasNext = (t + 1 < numTiles);
        if (hasNext) {
            const int k0 = (t + 1) * 8;
            #pragma unroll
            for (int j = 0; j < 4; j++) {
                int kg = k0 + aKoff + j;
                an[j] = (kg < K) ? Arow[kg] : 0.0f;
            }
            int kb = k0 + bKoff;
            if (kb < K) bn = *(const float4*)(Wsel + (size_t)kb * 64);
        }

        // ---- compute on current buffer ----
        #pragma unroll
        for (int kk = 0; kk < 8; kk++) {
            float a[8], b[8];
            #pragma unroll
            for (int i = 0; i < 8; i++) a[i] = As[buf][kk][mBase + i];
            #pragma unroll
            for (int j = 0; j < 8; j++) b[j] = Bs[buf][kk][nBase + j];
            #pragma unroll
            for (int i = 0; i < 8; i++)
                #pragma unroll
                for (int j = 0; j < 8; j++)
                    acc[i][j] = fmaf(a[i], b[j], acc[i][j]);
        }

        // ---- stage next tile into the other buffer ----
        if (hasNext) {
            const int nb = buf ^ 1;
            #pragma unroll
            for (int j = 0; j < 4; j++)
                As[nb][aKoff + j][aRow] = an[j];
            *(float4*)&Bs[nb][bKoff][bNoff] = bn;
        }
        __syncthreads();
        buf ^= 1;
    }

    // ---- write C tile ----
    float* Crow = g_Ebig + (size_t)(blockIdx.x * 128 + mBase) * 256 + colOff + nBase;
    #pragma unroll
    for (int i = 0; i < 8; i++) {
        *(float4*)(Crow + (size_t)i * 256)     = make_float4(acc[i][0], acc[i][1], acc[i][2], acc[i][3]);
        *(float4*)(Crow + (size_t)i * 256 + 4) = make_float4(acc[i][4], acc[i][5], acc[i][6], acc[i][7]);
    }
}

// ---------------------------------------------------------------------------
// Epilogue: one warp per row.
//   - linear dot over the full row (coalesced strided scan)
//   - 8 small embeddings computed on the fly from cols 2626..2667
//   - factored cross:
//       au*(gu+ou+uu) + gu*(ou+uu) + ou*uu + (ai+gi+oi+ui)*(mu+tu) + mi*ti
//   - warp reduce, sigmoid
// ---------------------------------------------------------------------------
__global__ __launch_bounds__(256)
void epilogue_kernel(const float* __restrict__ fv,
                     const float* __restrict__ Wau, const float* __restrict__ Wai,
                     const float* __restrict__ Wgu, const float* __restrict__ Wgi,
                     const float* __restrict__ Wou, const float* __restrict__ Woi,
                     const float* __restrict__ Wmu, const float* __restrict__ Wmi,
                     const float* __restrict__ linw, const float* __restrict__ linb,
                     float* __restrict__ out)
{
    const int row  = (blockIdx.x * blockDim.x + threadIdx.x) >> 5;
    const int lane = threadIdx.x & 31;
    if (row >= B_ROWS) return;

    const float* r = fv + (size_t)row * F_DIM;

    // linear term (partial per lane)
    float lin = 0.0f;
    for (int k = lane; k < F_DIM; k += 32)
        lin += r[k] * linw[k];

    // small-feature values (broadcast loads: all lanes same address, L1-hot)
    float fs[42];
    #pragma unroll
    for (int j = 0; j < 42; j++) fs[j] = r[2626 + j];

    const float* E = g_Ebig + (size_t)row * 256;

    float cross = 0.0f;
    #pragma unroll
    for (int h = 0; h < 2; h++) {
        const int d = lane + h * 32;

        float au = fs[0] * Wau[d];
        float ai = fs[0] * Wai[d];
        float gu = fs[0] * Wgu[d] + fs[1] * Wgu[64 + d];
        float gi = fs[0] * Wgi[d] + fs[1] * Wgi[64 + d];

        float ou = 0.0f, oi = 0.0f;
        #pragma unroll
        for (int j = 0; j < 21; j++) {
            ou = fmaf(fs[2 + j], Wou[j * 64 + d], ou);
            oi = fmaf(fs[2 + j], Woi[j * 64 + d], oi);
        }
        float mu = 0.0f, mi = 0.0f;
        #pragma unroll
        for (int j = 0; j < 19; j++) {
            mu = fmaf(fs[23 + j], Wmu[j * 64 + d], mu);
            mi = fmaf(fs[23 + j], Wmi[j * 64 + d], mi);
        }

        const float uu = E[d];
        const float ui = E[64 + d];
        const float tu = E[128 + d];
        const float ti = E[192 + d];

        const float ouu = ou + uu;
        const float mt  = mu + tu;
        cross += au * (gu + ouu)
               + gu * ouu
               + ou * uu
               + (ai + gi + oi + ui) * mt
               + mi * ti;
    }

    float tot = lin + cross;
    #pragma unroll
    for (int o = 16; o > 0; o >>= 1)
        tot += __shfl_xor_sync(0xffffffffu, tot, o);

    if (lane == 0) {
        const float logit = tot + linb[0];
        out[row] = 1.0f / (1.0f + expf(-logit));
    }
}

// ---------------------------------------------------------------------------
extern "C" void kernel_launch(void* const* d_in, const int* in_sizes, int n_in,
                              void* d_out, int out_size)
{
    const float* fv  = (const float*)d_in[0];
    const float* Wau = (const float*)d_in[1];
    const float* Wai = (const float*)d_in[2];
    const float* Wgu = (const float*)d_in[3];
    const float* Wgi = (const float*)d_in[4];
    const float* Wou = (const float*)d_in[5];
    const float* Woi = (const float*)d_in[6];
    const float* Wmu = (const float*)d_in[7];
    const float* Wmi = (const float*)d_in[8];
    const float* Wuu = (const float*)d_in[9];
    const float* Wui = (const float*)d_in[10];
    const float* Wtu = (const float*)d_in[11];
    const float* Wti = (const float*)d_in[12];
    const float* lnw = (const float*)d_in[13];
    const float* lnb = (const float*)d_in[14];
    float* out = (float*)d_out;

    // Big embeddings: uu|ui from cols [0,943), tu|ti from cols [943,2625)
    gemm128_kernel<<<B_ROWS / 128, 256>>>(fv,        943,  Wuu, Wui, 0);
    gemm128_kernel<<<B_ROWS / 128, 256>>>(fv + 943, 1682,  Wtu, Wti, 128);

    // Fused linear + small embeddings + cross + sigmoid (1 warp / row)
    epilogue_kernel<<<B_ROWS / 8, 256>>>(fv, Wau, Wai, Wgu, Wgi, Wou, Woi,
                                         Wmu, Wmi, lnw, lnb, out);
}

// round 7
// speedup vs baseline: 1.3815x; 1.3815x over previous
#include <cuda_runtime.h>
#include <cuda_bf16.h>
#include <math.h>
#include <stdint.h>

#define B_ROWS 32768
#define F_DIM  2668

// ---------------------------------------------------------------------------
// Device scratch
// ---------------------------------------------------------------------------
// Big-embedding outputs: [B, 256] = uu|ui|tu|ti (64 cols each), fp32
__device__ float g_Ebig[(size_t)B_ROWS * 256];

// Pre-split, transposed weights for the two big GEMMs.
// Layout: [n][k] row-major, n in 0..127 (W0 cols | W1 cols), k zero-padded.
#define KP1 960    // userid: K=943  -> 30 chunks of 32
#define KP2 1728   // itemid: K=1682 -> 53 chunks of 32 (covers 1696, pad zeros)
__device__ __align__(16) __nv_bfloat16 g_Bhi1[128 * KP1];
__device__ __align__(16) __nv_bfloat16 g_Blo1[128 * KP1];
__device__ __align__(16) __nv_bfloat16 g_Bhi2[128 * KP2];
__device__ __align__(16) __nv_bfloat16 g_Blo2[128 * KP2];

// ---------------------------------------------------------------------------
// mma.sync m16n8k16 bf16 (base sm_80+ PTX -> HMMA on tensor pipe; no tcgen05,
// which the harness's compute_103 PTX target cannot assemble)
// ---------------------------------------------------------------------------
__device__ __forceinline__ void mma16816(float* c, const uint32_t* a, const uint32_t* b) {
    asm volatile("mma.sync.aligned.m16n8k16.row.col.f32.bf16.bf16.f32 "
        "{%0,%1,%2,%3}, {%4,%5,%6,%7}, {%8,%9}, {%0,%1,%2,%3};"
        : "+f"(c[0]), "+f"(c[1]), "+f"(c[2]), "+f"(c[3])
        : "r"(a[0]), "r"(a[1]), "r"(a[2]), "r"(a[3]), "r"(b[0]), "r"(b[1]));
}

// ---------------------------------------------------------------------------
// Prep kernel: split+transpose big-embedding weights into bf16 hi/lo, [n][k]
// ---------------------------------------------------------------------------
__global__ __launch_bounds__(256)
void prep_B_kernel(const float* __restrict__ Wuu, const float* __restrict__ Wui,
                   const float* __restrict__ Wtu, const float* __restrict__ Wti)
{
    const int idx = blockIdx.x * 256 + threadIdx.x;
    const int N1 = 128 * KP1;
    if (idx < N1) {
        const int n = idx / KP1, k = idx % KP1;
        float v = 0.0f;
        if (k < 943) v = (n < 64) ? Wuu[k * 64 + n] : Wui[k * 64 + (n - 64)];
        __nv_bfloat16 h = __float2bfloat16(v);
        __nv_bfloat16 l = __float2bfloat16(v - __bfloat162float(h));
        g_Bhi1[idx] = h;
        g_Blo1[idx] = l;
    } else if (idx < N1 + 128 * KP2) {
        const int j = idx - N1;
        const int n = j / KP2, k = j % KP2;
        float v = 0.0f;
        if (k < 1682) v = (n < 64) ? Wtu[k * 64 + n] : Wti[k * 64 + (n - 64)];
        __nv_bfloat16 h = __float2bfloat16(v);
        __nv_bfloat16 l = __float2bfloat16(v - __bfloat162float(h));
        g_Bhi2[j] = h;
        g_Blo2[j] = l;
    }
}

// ---------------------------------------------------------------------------
// Split-bf16 warp-MMA GEMM.
// grid = 512: blocks [0,256) userid (K=943), [256,512) itemid (K=1682).
// Per CTA: C[128,128] = A[128,K] @ W[K,128] via AhBh + AhBl + AlBh, fp32 accum.
// 256 threads = 8 warps, warp grid 4(M) x 2(N), warp tile 32x64.
// ---------------------------------------------------------------------------
#define SPAD 40   // smem row pad (bf16): 40*2B = 80B -> conflict-free quad pattern

__global__ __launch_bounds__(256)
void gemm_mma_kernel(const float* __restrict__ fv)
{
    __shared__ __nv_bfloat16 As_hi[128][SPAD];
    __shared__ __nv_bfloat16 As_lo[128][SPAD];
    __shared__ __nv_bfloat16 Bs_hi[128][SPAD];
    __shared__ __nv_bfloat16 Bs_lo[128][SPAD];

    const int tid  = threadIdx.x;
    const int lane = tid & 31;
    const int wid  = tid >> 5;
    const int warp_m = (wid & 3) * 32;   // 0,32,64,96
    const int warp_n = (wid >> 2) * 64;  // 0,64

    const int g      = blockIdx.x >> 8;
    const int mtile  = blockIdx.x & 255;
    const int K      = g ? 1682 : 943;
    const int Kp     = g ? KP2 : KP1;
    const int nchunks = g ? (KP2 >> 5) : (KP1 >> 5);   // 53 covers 1696<=1728 / 30
    const int colOff = g ? 128 : 0;
    const __nv_bfloat16* __restrict__ Bh = g ? g_Bhi2 : g_Bhi1;
    const __nv_bfloat16* __restrict__ Bl = g ? g_Blo2 : g_Blo1;
    const float* __restrict__ Abase = fv + (size_t)(mtile * 128) * F_DIM + (g ? 943 : 0);

    float acc[2][8][4];
    #pragma unroll
    for (int i = 0; i < 2; i++)
        #pragma unroll
        for (int j = 0; j < 8; j++)
            #pragma unroll
            for (int q = 0; q < 4; q++) acc[i][j][q] = 0.0f;

    for (int t = 0; t < nchunks; ++t) {
        const int k0 = t << 5;

        // ---- A chunk: 128 rows x 32 cols fp32 -> bf16 hi/lo (2 cols/thread/iter)
        #pragma unroll
        for (int i = 0; i < 8; ++i) {
            const int slot = tid + (i << 8);          // 0..2047
            const int row  = slot >> 4;
            const int col  = (slot & 15) << 1;
            const int gc   = k0 + col;
            const float v0 = (gc     < K) ? Abase[(size_t)row * F_DIM + gc]     : 0.0f;
            const float v1 = (gc + 1 < K) ? Abase[(size_t)row * F_DIM + gc + 1] : 0.0f;
            const __nv_bfloat162 h2 = __floats2bfloat162_rn(v0, v1);
            const float l0 = v0 - __low2float(h2);
            const float l1 = v1 - __high2float(h2);
            const __nv_bfloat162 l2 = __floats2bfloat162_rn(l0, l1);
            *(__nv_bfloat162*)&As_hi[row][col] = h2;
            *(__nv_bfloat162*)&As_lo[row][col] = l2;
        }
        // ---- B chunk: 128 n-rows x 32 k-cols, pre-split bf16 (uint4 = 8 bf16)
        #pragma unroll
        for (int i = 0; i < 2; ++i) {
            const int slot = tid + (i << 8);          // 0..511
            const int n  = slot >> 2;
            const int k8 = (slot & 3) << 3;
            const size_t off = (size_t)n * Kp + k0 + k8;
            *(uint4*)&Bs_hi[n][k8] = *(const uint4*)(Bh + off);
            *(uint4*)&Bs_lo[n][k8] = *(const uint4*)(Bl + off);
        }
        __syncthreads();

        // ---- compute: 2 k16 steps x (2 mfrag x 8 nfrag x 3 split products)
        #pragma unroll
        for (int ks = 0; ks < 32; ks += 16) {
            const int fr = (lane >> 2);          // 0..7
            const int fc = ks + ((lane & 3) << 1);

            uint32_t ah[2][4], al[2][4];
            #pragma unroll
            for (int mf = 0; mf < 2; ++mf) {
                const int r0 = warp_m + mf * 16 + fr;
                ah[mf][0] = *(const uint32_t*)&As_hi[r0    ][fc    ];
                ah[mf][1] = *(const uint32_t*)&As_hi[r0 + 8][fc    ];
                ah[mf][2] = *(const uint32_t*)&As_hi[r0    ][fc + 8];
                ah[mf][3] = *(const uint32_t*)&As_hi[r0 + 8][fc + 8];
                al[mf][0] = *(const uint32_t*)&As_lo[r0    ][fc    ];
                al[mf][1] = *(const uint32_t*)&As_lo[r0 + 8][fc    ];
                al[mf][2] = *(const uint32_t*)&As_lo[r0    ][fc + 8];
                al[mf][3] = *(const uint32_t*)&As_lo[r0 + 8][fc + 8];
            }
            #pragma unroll
            for (int nf = 0; nf < 8; ++nf) {
                const int n0 = warp_n + nf * 8 + fr;
                uint32_t bh[2], bl[2];
                bh[0] = *(const uint32_t*)&Bs_hi[n0][fc    ];
                bh[1] = *(const uint32_t*)&Bs_hi[n0][fc + 8];
                bl[0] = *(const uint32_t*)&Bs_lo[n0][fc    ];
                bl[1] = *(const uint32_t*)&Bs_lo[n0][fc + 8];
                #pragma unroll
                for (int mf = 0; mf < 2; ++mf) {
                    mma16816(acc[mf][nf], ah[mf], bh);   // Ah*Bh
                    mma16816(acc[mf][nf], ah[mf], bl);   // Ah*Bl
                    mma16816(acc[mf][nf], al[mf], bh);   // Al*Bh
                }
            }
        }
        __syncthreads();
    }

    // ---- write C: per frag, (c0,c1) and (c2,c3) are consecutive cols -> float2
    #pragma unroll
    for (int mf = 0; mf < 2; ++mf) {
        const int row0 = mtile * 128 + warp_m + mf * 16 + (lane >> 2);
        #pragma unroll
        for (int nf = 0; nf < 8; ++nf) {
            const int col = colOff + warp_n + nf * 8 + ((lane & 3) << 1);
            float* p0 = g_Ebig + (size_t)row0 * 256 + col;
            *(float2*)p0                       = make_float2(acc[mf][nf][0], acc[mf][nf][1]);
            *(float2*)(p0 + (size_t)8 * 256)   = make_float2(acc[mf][nf][2], acc[mf][nf][3]);
        }
    }
}

// ---------------------------------------------------------------------------
// Epilogue: one warp per row.
//   float4 linear dot (2668 = 667 float4 exactly) + 8 small embeddings
//   + factored cross + sigmoid
// ---------------------------------------------------------------------------
__global__ __launch_bounds__(256)
void epilogue_kernel(const float* __restrict__ fv,
                     const float* __restrict__ Wau, const float* __restrict__ Wai,
                     const float* __restrict__ Wgu, const float* __restrict__ Wgi,
                     const float* __restrict__ Wou, const float* __restrict__ Woi,
                     const float* __restrict__ Wmu, const float* __restrict__ Wmi,
                     const float* __restrict__ linw, const float* __restrict__ linb,
                     float* __restrict__ out)
{
    const int row  = (blockIdx.x * blockDim.x + threadIdx.x) >> 5;
    const int lane = threadIdx.x & 31;
    if (row >= B_ROWS) return;

    const float* r = fv + (size_t)row * F_DIM;
    const float4* r4 = (const float4*)r;        // row start is 16B-aligned (2668*4B stride)
    const float4* w4 = (const float4*)linw;

    // linear term: 667 float4 per row, 4 independent accumulators for MLP
    float la = 0.0f, lb = 0.0f, lc = 0.0f, ld2 = 0.0f;
    #pragma unroll
    for (int it = 0; it < 21; ++it) {
        const int idx = lane + (it << 5);
        if (it < 20 || idx < 667) {
            const float4 rv = r4[idx];
            const float4 wv = w4[idx];
            la  = fmaf(rv.x, wv.x, la);
            lb  = fmaf(rv.y, wv.y, lb);
            lc  = fmaf(rv.z, wv.z, lc);
            ld2 = fmaf(rv.w, wv.w, ld2);
        }
    }
    float lin = (la + lb) + (lc + ld2);

    // small-feature values (broadcast loads, L1-hot)
    float fs[42];
    #pragma unroll
    for (int j = 0; j < 42; j++) fs[j] = r[2626 + j];

    const float* E = g_Ebig + (size_t)row * 256;

    float cross = 0.0f;
    #pragma unroll
    for (int h = 0; h < 2; h++) {
        const int d = lane + h * 32;

        float au = fs[0] * Wau[d];
        float ai = fs[0] * Wai[d];
        float gu = fs[0] * Wgu[d] + fs[1] * Wgu[64 + d];
        float gi = fs[0] * Wgi[d] + fs[1] * Wgi[64 + d];

        float ou = 0.0f, oi = 0.0f;
        #pragma unroll
        for (int j = 0; j < 21; j++) {
            ou = fmaf(fs[2 + j], Wou[j * 64 + d], ou);
            oi = fmaf(fs[2 + j], Woi[j * 64 + d], oi);
        }
        float mu = 0.0f, mi = 0.0f;
        #pragma unroll
        for (int j = 0; j < 19; j++) {
            mu = fmaf(fs[23 + j], Wmu[j * 64 + d], mu);
            mi = fmaf(fs[23 + j], Wmi[j * 64 + d], mi);
        }

        const float uu = E[d];
        const float ui = E[64 + d];
        const float tu = E[128 + d];
        const float ti = E[192 + d];

        const float ouu = ou + uu;
        const float mt  = mu + tu;
        cross += au * (gu + ouu)
               + gu * ouu
               + ou * uu
               + (ai + gi + oi + ui) * mt
               + mi * ti;
    }

    float tot = lin + cross;
    #pragma unroll
    for (int o = 16; o > 0; o >>= 1)
        tot += __shfl_xor_sync(0xffffffffu, tot, o);

    if (lane == 0) {
        const float logit = tot + linb[0];
        out[row] = 1.0f / (1.0f + expf(-logit));
    }
}

// ---------------------------------------------------------------------------
extern "C" void kernel_launch(void* const* d_in, const int* in_sizes, int n_in,
                              void* d_out, int out_size)
{
    const float* fv  = (const float*)d_in[0];
    const float* Wau = (const float*)d_in[1];
    const float* Wai = (const float*)d_in[2];
    const float* Wgu = (const float*)d_in[3];
    const float* Wgi = (const float*)d_in[4];
    const float* Wou = (const float*)d_in[5];
    const float* Woi = (const float*)d_in[6];
    const float* Wmu = (const float*)d_in[7];
    const float* Wmi = (const float*)d_in[8];
    const float* Wuu = (const float*)d_in[9];
    const float* Wui = (const float*)d_in[10];
    const float* Wtu = (const float*)d_in[11];
    const float* Wti = (const float*)d_in[12];
    const float* lnw = (const float*)d_in[13];
    const float* lnb = (const float*)d_in[14];
    float* out = (float*)d_out;

    // 1. split+transpose big weights (bf16 hi/lo, zero-padded K)
    const int prepTotal = 128 * KP1 + 128 * KP2;
    prep_B_kernel<<<(prepTotal + 255) / 256, 256>>>(Wuu, Wui, Wtu, Wti);

    // 2. warp-MMA split-bf16 GEMMs (userid + itemid in one grid)
    gemm_mma_kernel<<<512, 256>>>(fv);

    // 3. fused linear + small embeddings + cross + sigmoid
    epilogue_kernel<<<B_ROWS / 8, 256>>>(fv, Wau, Wai, Wgu, Wgi, Wou, Woi,
                                         Wmu, Wmi, lnw, lnb, out);
}

// round 8
// speedup vs baseline: 1.8714x; 1.3546x over previous
#include <cuda_runtime.h>
#include <cuda_bf16.h>
#include <math.h>
#include <stdint.h>

#define B_ROWS 32768
#define F_DIM  2668

// Big-GEMM K geometry. userid: fv cols [0,943). itemid: fv cols [943,2625),
// processed from aligned base col 940 with k in [3,1685) valid (mask first 3).
#define KP1 960     // 30 chunks of 32
#define KP2 1696    // 53 chunks of 32
#define NC1 30
#define NC2 53

// ---------------------------------------------------------------------------
// Device scratch
// ---------------------------------------------------------------------------
__device__ float g_Ebig[(size_t)B_ROWS * 256];   // uu|ui|tu|ti
__device__ float g_Lin[2][B_ROWS];               // linear partials (userid/itemid cols)

__device__ __align__(16) __nv_bfloat16 g_Bhi1[128 * KP1];
__device__ __align__(16) __nv_bfloat16 g_Blo1[128 * KP1];
__device__ __align__(16) __nv_bfloat16 g_Bhi2[128 * KP2];
__device__ __align__(16) __nv_bfloat16 g_Blo2[128 * KP2];

// ---------------------------------------------------------------------------
// PTX helpers (all base PTX features, assemble at compute_103)
// ---------------------------------------------------------------------------
__device__ __forceinline__ uint32_t smem_u32(const void* p) {
    uint32_t a;
    asm("{ .reg .u64 t; cvta.to.shared.u64 t, %1; cvt.u32.u64 %0, t; }"
        : "=r"(a) : "l"(p));
    return a;
}

__device__ __forceinline__ void mma16816(float* c, const uint32_t* a, const uint32_t* b) {
    asm volatile("mma.sync.aligned.m16n8k16.row.col.f32.bf16.bf16.f32 "
        "{%0,%1,%2,%3}, {%4,%5,%6,%7}, {%8,%9}, {%0,%1,%2,%3};"
        : "+f"(c[0]), "+f"(c[1]), "+f"(c[2]), "+f"(c[3])
        : "r"(a[0]), "r"(a[1]), "r"(a[2]), "r"(a[3]), "r"(b[0]), "r"(b[1]));
}

__device__ __forceinline__ void ldsm_x4(uint32_t* r, uint32_t addr) {
    asm volatile("ldmatrix.sync.aligned.m8n8.x4.shared.b16 {%0,%1,%2,%3}, [%4];"
        : "=r"(r[0]), "=r"(r[1]), "=r"(r[2]), "=r"(r[3]) : "r"(addr));
}

__device__ __forceinline__ void cp16(uint32_t dst, const void* src) {
    asm volatile("cp.async.cg.shared.global [%0], [%1], 16;" :: "r"(dst), "l"(src));
}
#define CP_COMMIT()  asm volatile("cp.async.commit_group;" ::: "memory")
#define CP_WAIT(n)   asm volatile("cp.async.wait_group %0;" :: "n"(n) : "memory")

// ---------------------------------------------------------------------------
// Prep: split+transpose big-embedding weights into bf16 hi/lo, [n][k] layout.
// itemid k index is shifted by +3 (k stores W[k-3] for 3<=k<1685).
// ---------------------------------------------------------------------------
__global__ __launch_bounds__(256)
void prep_B_kernel(const float* __restrict__ Wuu, const float* __restrict__ Wui,
                   const float* __restrict__ Wtu, const float* __restrict__ Wti)
{
    const int idx = blockIdx.x * 256 + threadIdx.x;
    const int N1 = 128 * KP1;
    if (idx < N1) {
        const int n = idx / KP1, k = idx % KP1;
        float v = 0.0f;
        if (k < 943) v = (n < 64) ? Wuu[k * 64 + n] : Wui[k * 64 + (n - 64)];
        __nv_bfloat16 h = __float2bfloat16(v);
        g_Bhi1[idx] = h;
        g_Blo1[idx] = __float2bfloat16(v - __bfloat162float(h));
    } else if (idx < N1 + 128 * KP2) {
        const int j = idx - N1;
        const int n = j / KP2, k = j % KP2;
        float v = 0.0f;
        if (k >= 3 && k < 1685)
            v = (n < 64) ? Wtu[(k - 3) * 64 + n] : Wti[(k - 3) * 64 + (n - 64)];
        __nv_bfloat16 h = __float2bfloat16(v);
        g_Bhi2[j] = h;
        g_Blo2[j] = __float2bfloat16(v - __bfloat162float(h));
    }
}

// ---------------------------------------------------------------------------
// Split-bf16 warp-MMA GEMM with cp.async double-buffering, ldmatrix frags,
// and fused linear-dot partials.
// grid = 512: blocks [0,256) itemid (long, first), [256,512) userid.
// CTA: 512 threads = 16 warps, warp grid 4(M) x 4(N), warp tile 32x32.
// smem rows are 80B (40 bf16): ldmatrix 8-row groups conflict-free.
// ---------------------------------------------------------------------------
#define SROW 80
#define ABYTES 10240               // 128 * 80
#define BUFSZ  (4 * ABYTES)        // AH, AL, BH, BL per buffer
#define AH_OFF(b) ((b) * BUFSZ)
#define AL_OFF(b) ((b) * BUFSZ + ABYTES)
#define BH_OFF(b) ((b) * BUFSZ + 2 * ABYTES)
#define BL_OFF(b) ((b) * BUFSZ + 3 * ABYTES)
#define LW_OFF    (2 * BUFSZ)                  // 81920
#define GEMM_SMEM (LW_OFF + KP2 * 4)           // 88704 bytes

// Convert one float4 (masked) to hi/lo bf16, store to smem, return linw dot.
__device__ __forceinline__ float cvt_row(char* smem, uint32_t ah, uint32_t al,
                                         int row, int col, float4 v, float4 lw,
                                         int gc0, int Klo, int Khi)
{
    float x0 = (gc0     >= Klo && gc0     < Khi) ? v.x : 0.0f;
    float x1 = (gc0 + 1 >= Klo && gc0 + 1 < Khi) ? v.y : 0.0f;
    float x2 = (gc0 + 2 >= Klo && gc0 + 2 < Khi) ? v.z : 0.0f;
    float x3 = (gc0 + 3 >= Klo && gc0 + 3 < Khi) ? v.w : 0.0f;
    float lin = fmaf(x0, lw.x, fmaf(x1, lw.y, fmaf(x2, lw.z, x3 * lw.w)));
    __nv_bfloat162 h0 = __floats2bfloat162_rn(x0, x1);
    __nv_bfloat162 h1 = __floats2bfloat162_rn(x2, x3);
    __nv_bfloat162 l0 = __floats2bfloat162_rn(x0 - __low2float(h0), x1 - __high2float(h0));
    __nv_bfloat162 l1 = __floats2bfloat162_rn(x2 - __low2float(h1), x3 - __high2float(h1));
    const uint32_t off = row * SROW + col * 2;
    *(__nv_bfloat162*)(smem + ah + off)     = h0;
    *(__nv_bfloat162*)(smem + ah + off + 4) = h1;
    *(__nv_bfloat162*)(smem + al + off)     = l0;
    *(__nv_bfloat162*)(smem + al + off + 4) = l1;
    return lin;
}

__global__ __launch_bounds__(512)
void gemm_mma_kernel(const float* __restrict__ fv, const float* __restrict__ lnw)
{
    extern __shared__ __align__(16) char smem[];
    const uint32_t sb = smem_u32(smem);
    const int tid = threadIdx.x, lane = tid & 31, wid = tid >> 5;
    const int warp_m = (wid & 3) * 32, warp_n = (wid >> 2) * 32;

    const int g     = (blockIdx.x < 256) ? 1 : 0;     // itemid first (load balance)
    const int mtile = blockIdx.x & 255;
    const int Klo = g ? 3 : 0, Khi = g ? 1685 : 943;
    const int KP  = g ? KP2 : KP1, nc = g ? NC2 : NC1;
    const int colOff = g ? 128 : 0;
    const __nv_bfloat16* __restrict__ Bh = g ? g_Bhi2 : g_Bhi1;
    const __nv_bfloat16* __restrict__ Bl = g ? g_Blo2 : g_Blo1;
    const float* __restrict__ Abase = fv + (size_t)(mtile * 128) * F_DIM + (g ? 940 : 0);
    const float* __restrict__ lwb   = lnw + (g ? 940 : 0);

    // stage (masked) linw slice into smem
    float* lw_s = (float*)(smem + LW_OFF);
    for (int k = tid; k < KP; k += 512)
        lw_s[k] = (k >= Klo && k < Khi) ? lwb[k] : 0.0f;

    // A load mapping: 2 float4/thread (rows arow0, arow0+64)
    const int arow0 = tid >> 3;
    const int acol  = (tid & 7) << 2;
    // B cp.async mapping: 1 x 16B hi + 1 x 16B lo per thread
    const int bn  = tid >> 2;
    const int bk8 = (tid & 3) << 3;

    float4 av0 = *(const float4*)(Abase + (size_t)arow0 * F_DIM + acol);
    float4 av1 = *(const float4*)(Abase + (size_t)(arow0 + 64) * F_DIM + acol);

    cp16(sb + BH_OFF(0) + bn * SROW + bk8 * 2, Bh + (size_t)bn * KP + bk8);
    cp16(sb + BL_OFF(0) + bn * SROW + bk8 * 2, Bl + (size_t)bn * KP + bk8);
    CP_COMMIT();
    __syncthreads();   // lw_s visible

    float acc[2][4][4];
    #pragma unroll
    for (int i = 0; i < 2; i++)
        #pragma unroll
        for (int j = 0; j < 4; j++)
            #pragma unroll
            for (int q = 0; q < 4; q++) acc[i][j][q] = 0.0f;

    float lin0 = 0.0f, lin1 = 0.0f;

    // per-lane ldmatrix address components
    const uint32_t aRowSel = (lane & 7) + ((lane >> 3) & 1) * 8;
    const uint32_t aKSel   = ((lane >> 4) & 1) * 8;

    for (int t = 0; t < nc; ++t) {
        const int b  = t & 1;
        const int k0 = t << 5;
        const bool hasN = (t + 1 < nc);

        float4 an0, an1;
        if (hasN) {
            const int k1 = k0 + 32;
            an0 = *(const float4*)(Abase + (size_t)arow0 * F_DIM + k1 + acol);
            an1 = *(const float4*)(Abase + (size_t)(arow0 + 64) * F_DIM + k1 + acol);
            cp16(sb + BH_OFF(b ^ 1) + bn * SROW + bk8 * 2, Bh + (size_t)bn * KP + k1 + bk8);
            cp16(sb + BL_OFF(b ^ 1) + bn * SROW + bk8 * 2, Bl + (size_t)bn * KP + k1 + bk8);
            CP_COMMIT();
        }

        // convert A(t) -> buf b, accumulate linear partials
        {
            const float4 lw4 = *(const float4*)(lw_s + k0 + acol);
            lin0 += cvt_row(smem, AH_OFF(b), AL_OFF(b), arow0,      acol, av0, lw4,
                            k0 + acol, Klo, Khi);
            lin1 += cvt_row(smem, AH_OFF(b), AL_OFF(b), arow0 + 64, acol, av1, lw4,
                            k0 + acol, Klo, Khi);
        }

        if (hasN) CP_WAIT(1); else CP_WAIT(0);
        __syncthreads();

        // compute chunk t
        #pragma unroll
        for (int ks = 0; ks < 32; ks += 16) {
            uint32_t ah[2][4], al[2][4], bh0[4], bh1[4], bl0[4], bl1[4];
            const uint32_t aoff = sb + AH_OFF(b)
                + (warp_m + aRowSel) * SROW + (ks + aKSel) * 2;
            ldsm_x4(ah[0], aoff);
            ldsm_x4(ah[1], aoff + 16 * SROW);
            ldsm_x4(al[0], aoff + ABYTES);
            ldsm_x4(al[1], aoff + ABYTES + 16 * SROW);
            const uint32_t boff = sb + BH_OFF(b) + (warp_n + lane) * SROW + ks * 2;
            ldsm_x4(bh0, boff);
            ldsm_x4(bh1, boff + 16);
            ldsm_x4(bl0, boff + ABYTES);
            ldsm_x4(bl1, boff + ABYTES + 16);
            #pragma unroll
            for (int nf = 0; nf < 4; ++nf) {
                uint32_t bhf[2] = { bh0[nf], bh1[nf] };
                uint32_t blf[2] = { bl0[nf], bl1[nf] };
                #pragma unroll
                for (int mf = 0; mf < 2; ++mf) {
                    mma16816(acc[mf][nf], ah[mf], bhf);
                    mma16816(acc[mf][nf], ah[mf], blf);
                    mma16816(acc[mf][nf], al[mf], bhf);
                }
            }
        }
        __syncthreads();
        av0 = an0; av1 = an1;
    }

    // linear partial reduce across the 8 threads sharing each row
    #pragma unroll
    for (int o = 4; o > 0; o >>= 1) {
        lin0 += __shfl_down_sync(0xffffffffu, lin0, o, 8);
        lin1 += __shfl_down_sync(0xffffffffu, lin1, o, 8);
    }
    if ((tid & 7) == 0) {
        g_Lin[g][mtile * 128 + arow0]      = lin0;
        g_Lin[g][mtile * 128 + arow0 + 64] = lin1;
    }

    // write C
    #pragma unroll
    for (int mf = 0; mf < 2; ++mf) {
        const int row0 = mtile * 128 + warp_m + mf * 16 + (lane >> 2);
        #pragma unroll
        for (int nf = 0; nf < 4; ++nf) {
            const int col = colOff + warp_n + nf * 8 + ((lane & 3) << 1);
            float* p = g_Ebig + (size_t)row0 * 256 + col;
            *(float2*)p                     = make_float2(acc[mf][nf][0], acc[mf][nf][1]);
            *(float2*)(p + (size_t)8 * 256) = make_float2(acc[mf][nf][2], acc[mf][nf][3]);
        }
    }
}

// ---------------------------------------------------------------------------
// Epilogue: one warp per row. Only reads fv cols [2625,2668) + g_Ebig + g_Lin.
// ---------------------------------------------------------------------------
__global__ __launch_bounds__(256)
void epilogue_kernel(const float* __restrict__ fv,
                     const float* __restrict__ Wau, const float* __restrict__ Wai,
                     const float* __restrict__ Wgu, const float* __restrict__ Wgi,
                     const float* __restrict__ Wou, const float* __restrict__ Woi,
                     const float* __restrict__ Wmu, const float* __restrict__ Wmi,
                     const float* __restrict__ linw, const float* __restrict__ linb,
                     float* __restrict__ out)
{
    const int row  = (blockIdx.x * blockDim.x + threadIdx.x) >> 5;
    const int lane = threadIdx.x & 31;
    if (row >= B_ROWS) return;

    const float* r = fv + (size_t)row * F_DIM;

    // linear tail: cols [2625, 2668)
    float part = r[2625 + lane] * linw[2625 + lane];
    if (lane < 11) part += r[2657 + lane] * linw[2657 + lane];

    // small-feature values (broadcast, L1-hot)
    float fs[42];
    #pragma unroll
    for (int j = 0; j < 42; j++) fs[j] = r[2626 + j];

    const float* E = g_Ebig + (size_t)row * 256;

    float cross = 0.0f;
    #pragma unroll
    for (int h = 0; h < 2; h++) {
        const int d = lane + h * 32;

        float au = fs[0] * Wau[d];
        float ai = fs[0] * Wai[d];
        float gu = fs[0] * Wgu[d] + fs[1] * Wgu[64 + d];
        float gi = fs[0] * Wgi[d] + fs[1] * Wgi[64 + d];

        float ou = 0.0f, oi = 0.0f;
        #pragma unroll
        for (int j = 0; j < 21; j++) {
            ou = fmaf(fs[2 + j], Wou[j * 64 + d], ou);
            oi = fmaf(fs[2 + j], Woi[j * 64 + d], oi);
        }
        float mu = 0.0f, mi = 0.0f;
        #pragma unroll
        for (int j = 0; j < 19; j++) {
            mu = fmaf(fs[23 + j], Wmu[j * 64 + d], mu);
            mi = fmaf(fs[23 + j], Wmi[j * 64 + d], mi);
        }

        const float uu = E[d];
        const float ui = E[64 + d];
        const float tu = E[128 + d];
        const float ti = E[192 + d];

        const float ouu = ou + uu;
        const float mt  = mu + tu;
        cross += au * (gu + ouu)
               + gu * ouu
               + ou * uu
               + (ai + gi + oi + ui) * mt
               + mi * ti;
    }

    float tot = part + cross;
    #pragma unroll
    for (int o = 16; o > 0; o >>= 1)
        tot += __shfl_xor_sync(0xffffffffu, tot, o);

    if (lane == 0) {
        const float lin = g_Lin[0][row] + g_Lin[1][row];
        const float logit = tot + lin + linb[0];
        out[row] = 1.0f / (1.0f + expf(-logit));
    }
}

// ---------------------------------------------------------------------------
extern "C" void kernel_launch(void* const* d_in, const int* in_sizes, int n_in,
                              void* d_out, int out_size)
{
    const float* fv  = (const float*)d_in[0];
    const float* Wau = (const float*)d_in[1];
    const float* Wai = (const float*)d_in[2];
    const float* Wgu = (const float*)d_in[3];
    const float* Wgi = (const float*)d_in[4];
    const float* Wou = (const float*)d_in[5];
    const float* Woi = (const float*)d_in[6];
    const float* Wmu = (const float*)d_in[7];
    const float* Wmi = (const float*)d_in[8];
    const float* Wuu = (const float*)d_in[9];
    const float* Wui = (const float*)d_in[10];
    const float* Wtu = (const float*)d_in[11];
    const float* Wti = (const float*)d_in[12];
    const float* lnw = (const float*)d_in[13];
    const float* lnb = (const float*)d_in[14];
    float* out = (float*)d_out;

    static int smem_set = 0;
    if (!smem_set) {
        cudaFuncSetAttribute(gemm_mma_kernel,
                             cudaFuncAttributeMaxDynamicSharedMemorySize, GEMM_SMEM);
        smem_set = 1;
    }

    const int prepTotal = 128 * (KP1 + KP2);
    prep_B_kernel<<<(prepTotal + 255) / 256, 256>>>(Wuu, Wui, Wtu, Wti);

    gemm_mma_kernel<<<512, 512, GEMM_SMEM>>>(fv, lnw);

    epilogue_kernel<<<B_ROWS / 8, 256>>>(fv, Wau, Wai, Wgu, Wgi, Wou, Woi,
                                         Wmu, Wmi, lnw, lnb, out);
}